// round 2
// baseline (speedup 1.0000x reference)
#include <cuda_runtime.h>
#include <cstdint>

// Problem constants (fixed by the dataset)
#define NN 100000
#define EE 1600000
#define F_IN 64
#define F_HID 64
#define F_OUT 32

// Scratch (static device globals — no allocation allowed)
__device__ __align__(16) float g_deg[NN];
__device__ __align__(16) float g_dis[NN];
__device__ __align__(16) float g_h1[NN * F_HID];     // X @ W1
__device__ __align__(16) float g_acc1[NN * F_HID];   // aggregated layer-1 output (pre-relu)
__device__ __align__(16) float g_h2[NN * F_OUT];     // relu(acc1) @ W2

// ---------------------------------------------------------------------------
// Degree / normalization
// ---------------------------------------------------------------------------
__global__ void k_zero_deg() {
    int i = blockIdx.x * blockDim.x + threadIdx.x;
    if (i < NN) g_deg[i] = 0.0f;
}

__global__ void k_degree(const int* __restrict__ dst) {
    int i = blockIdx.x * blockDim.x + threadIdx.x;
    if (i < EE) atomicAdd(&g_deg[dst[i]], 1.0f);
}

__global__ void k_dis() {
    int i = blockIdx.x * blockDim.x + threadIdx.x;
    if (i < NN) g_dis[i] = rsqrtf(g_deg[i] + 1.0f);
}

// ---------------------------------------------------------------------------
// Layer 1 GEMM: h1 = x @ W1 ; acc1 = h1 * dis^2 + b1   (self-loop term seed)
// blockDim = 256: col = tid & 63, row-in-tile = tid >> 6 (4 nodes / iter)
// Each block covers 64 nodes (16 iterations).
// ---------------------------------------------------------------------------
__global__ void k_gemm1(const float* __restrict__ x,
                        const float* __restrict__ W,
                        const float* __restrict__ b) {
    __shared__ float Ws[F_IN * F_HID];  // 16 KB
    __shared__ float bs[F_HID];
    __shared__ float xs[4 * F_IN];

    for (int i = threadIdx.x; i < F_IN * F_HID; i += 256) Ws[i] = W[i];
    if (threadIdx.x < F_HID) bs[threadIdx.x] = b[threadIdx.x];

    const int col = threadIdx.x & 63;
    const int r   = threadIdx.x >> 6;
    const int nb0 = blockIdx.x * 64;

    for (int it = 0; it < 16; it++) {
        const int nb = nb0 + it * 4;
        const int n  = nb + r;
        __syncthreads();
        xs[threadIdx.x] = (n < NN) ? x[n * F_IN + col] : 0.0f;
        __syncthreads();
        if (n < NN) {
            float acc = 0.0f;
#pragma unroll
            for (int k = 0; k < F_IN; k++)
                acc = fmaf(xs[r * F_IN + k], Ws[k * F_HID + col], acc);
            g_h1[n * F_HID + col] = acc;
            const float d = g_dis[n];
            g_acc1[n * F_HID + col] = fmaf(acc, d * d, bs[col]);
        }
    }
}

// ---------------------------------------------------------------------------
// Layer 1 scatter: acc1[dst] += h1[src] * (dis[src]*dis[dst])
// 16 threads per edge, float4 gather, 4 scalar atomicAdds.
// ---------------------------------------------------------------------------
__global__ void k_scatter1(const int* __restrict__ src,
                           const int* __restrict__ dst) {
    long long t = (long long)blockIdx.x * blockDim.x + threadIdx.x;
    if (t >= (long long)EE * 16) return;
    const int e    = (int)(t >> 4);
    const int part = (int)(t & 15);
    const int s = src[e];
    const int d = dst[e];
    const float norm = g_dis[s] * g_dis[d];
    const float4 v = *reinterpret_cast<const float4*>(&g_h1[s * F_HID + part * 4]);
    float* o = &g_acc1[d * F_HID + part * 4];
    atomicAdd(o + 0, v.x * norm);
    atomicAdd(o + 1, v.y * norm);
    atomicAdd(o + 2, v.z * norm);
    atomicAdd(o + 3, v.w * norm);
}

// ---------------------------------------------------------------------------
// Layer 2 GEMM: h2 = relu(acc1) @ W2 ; out = h2 * dis^2 + b2
// blockDim = 256: col = tid & 31, row-in-tile = tid >> 5 (8 nodes / iter)
// Each block covers 64 nodes (8 iterations).
// ---------------------------------------------------------------------------
__global__ void k_gemm2(const float* __restrict__ W,
                        const float* __restrict__ b,
                        float* __restrict__ out) {
    __shared__ float Ws[F_HID * F_OUT];  // 8 KB
    __shared__ float bs[F_OUT];
    __shared__ float xs[8 * F_HID];      // 2 KB

    for (int i = threadIdx.x; i < F_HID * F_OUT; i += 256) Ws[i] = W[i];
    if (threadIdx.x < F_OUT) bs[threadIdx.x] = b[threadIdx.x];

    const int col = threadIdx.x & 31;
    const int r   = threadIdx.x >> 5;
    const int nb0 = blockIdx.x * 64;

    for (int it = 0; it < 8; it++) {
        const int nb = nb0 + it * 8;
        __syncthreads();
        for (int j = threadIdx.x; j < 8 * F_HID; j += 256) {
            const int rr = j >> 6;
            const int kk = j & 63;
            const int n  = nb + rr;
            xs[j] = (n < NN) ? fmaxf(g_acc1[n * F_HID + kk], 0.0f) : 0.0f;
        }
        __syncthreads();
        const int n = nb + r;
        if (n < NN) {
            float acc = 0.0f;
#pragma unroll
            for (int k = 0; k < F_HID; k++)
                acc = fmaf(xs[r * F_HID + k], Ws[k * F_OUT + col], acc);
            g_h2[n * F_OUT + col] = acc;
            const float d = g_dis[n];
            out[n * F_OUT + col] = fmaf(acc, d * d, bs[col]);
        }
    }
}

// ---------------------------------------------------------------------------
// Layer 2 scatter: out[dst] += h2[src] * norm     (8 threads per edge)
// ---------------------------------------------------------------------------
__global__ void k_scatter2(const int* __restrict__ src,
                           const int* __restrict__ dst,
                           float* __restrict__ out) {
    long long t = (long long)blockIdx.x * blockDim.x + threadIdx.x;
    if (t >= (long long)EE * 8) return;
    const int e    = (int)(t >> 3);
    const int part = (int)(t & 7);
    const int s = src[e];
    const int d = dst[e];
    const float norm = g_dis[s] * g_dis[d];
    const float4 v = *reinterpret_cast<const float4*>(&g_h2[s * F_OUT + part * 4]);
    float* o = &out[d * F_OUT + part * 4];
    atomicAdd(o + 0, v.x * norm);
    atomicAdd(o + 1, v.y * norm);
    atomicAdd(o + 2, v.z * norm);
    atomicAdd(o + 3, v.w * norm);
}

// ---------------------------------------------------------------------------
extern "C" void kernel_launch(void* const* d_in, const int* in_sizes, int n_in,
                              void* d_out, int out_size) {
    const float* x  = (const float*)d_in[0];
    const int*   ei = (const int*)d_in[1];   // [2, E] (int64 in ref, int32 on device)
    const float* W1 = (const float*)d_in[2];
    const float* b1 = (const float*)d_in[3];
    const float* W2 = (const float*)d_in[4];
    const float* b2 = (const float*)d_in[5];
    float*       out = (float*)d_out;

    const int* src = ei;
    const int* dst = ei + EE;

    // degree + normalization
    k_zero_deg<<<(NN + 255) / 256, 256>>>();
    k_degree<<<(EE + 255) / 256, 256>>>(dst);
    k_dis<<<(NN + 255) / 256, 256>>>();

    // layer 1
    k_gemm1<<<(NN + 63) / 64, 256>>>(x, W1, b1);
    {
        long long threads = (long long)EE * 16;
        k_scatter1<<<(unsigned)((threads + 255) / 256), 256>>>(src, dst);
    }

    // layer 2 (relu fused into gemm2 input load; out seeded with self-loop term)
    k_gemm2<<<(NN + 63) / 64, 256>>>(W2, b2, out);
    {
        long long threads = (long long)EE * 8;
        k_scatter2<<<(unsigned)((threads + 255) / 256), 256>>>(src, dst, out);
    }
}

// round 3
// speedup vs baseline: 1.3629x; 1.3629x over previous
#include <cuda_runtime.h>
#include <cstdint>

#define NN 100000
#define EE 1600000
#define F_IN 64
#define F_HID 64
#define F_OUT 32

// Scratch (static device globals — no allocation allowed)
__device__ __align__(16) float g_deg[NN];
__device__ __align__(16) float g_dis[NN];
__device__ __align__(16) float g_norm[EE];           // dis[src]*dis[dst] per edge
__device__ __align__(16) float g_h1[NN * F_HID];     // X @ W1
__device__ __align__(16) float g_acc1[NN * F_HID];   // aggregated layer-1 (pre-relu)
__device__ __align__(16) float g_h2[NN * F_OUT];     // relu(acc1) @ W2

// ---------------------------------------------------------------------------
// Degree / normalization
// ---------------------------------------------------------------------------
__global__ void k_zero_deg() {
    int i = blockIdx.x * blockDim.x + threadIdx.x;
    if (i < NN) g_deg[i] = 0.0f;
}

__global__ void k_degree(const int* __restrict__ dst) {
    int i = blockIdx.x * blockDim.x + threadIdx.x;
    if (i < EE) atomicAdd(&g_deg[dst[i]], 1.0f);
}

__global__ void k_dis() {
    int i = blockIdx.x * blockDim.x + threadIdx.x;
    if (i < NN) g_dis[i] = rsqrtf(g_deg[i] + 1.0f);
}

__global__ void k_norm(const int* __restrict__ src, const int* __restrict__ dst) {
    int e = blockIdx.x * blockDim.x + threadIdx.x;
    if (e < EE) g_norm[e] = g_dis[src[e]] * g_dis[dst[e]];
}

// ---------------------------------------------------------------------------
// Layer 1 GEMM: h1 = x @ W1 ; acc1 = h1 * dis^2 + b1 (self-loop seed)
// 256 threads: col = tid & 63. Each thread holds W[:,col] in 64 registers.
// Tile = 4 nodes; x rows staged in smem, read as broadcast LDS.128.
// ---------------------------------------------------------------------------
__global__ void __launch_bounds__(256) k_gemm1(const float* __restrict__ x,
                                               const float* __restrict__ W,
                                               const float* __restrict__ b) {
    __shared__ float Ws[F_IN * F_HID];   // 16 KB
    __shared__ __align__(16) float xs[4 * F_IN];

    for (int i = threadIdx.x; i < F_IN * F_HID; i += 256) Ws[i] = W[i];
    __syncthreads();

    const int col = threadIdx.x & 63;
    float w[F_IN];
#pragma unroll
    for (int k = 0; k < F_IN; k++) w[k] = Ws[k * F_HID + col];
    const float bias = b[col];

    const int ntiles = NN / 4;   // 25000
    for (int tile = blockIdx.x; tile < ntiles; tile += gridDim.x) {
        const int nb = tile * 4;
        __syncthreads();
        xs[threadIdx.x] = x[nb * F_IN + threadIdx.x];
        __syncthreads();

        float a0 = 0.f, a1 = 0.f, a2 = 0.f, a3 = 0.f;
        const float4* xv = reinterpret_cast<const float4*>(xs);
#pragma unroll
        for (int k4 = 0; k4 < 16; k4++) {
            const float4 r0 = xv[k4];
            const float4 r1 = xv[16 + k4];
            const float4 r2 = xv[32 + k4];
            const float4 r3 = xv[48 + k4];
            const float w0 = w[4 * k4 + 0], w1 = w[4 * k4 + 1];
            const float w2 = w[4 * k4 + 2], w3 = w[4 * k4 + 3];
            a0 = fmaf(r0.x, w0, a0); a0 = fmaf(r0.y, w1, a0);
            a0 = fmaf(r0.z, w2, a0); a0 = fmaf(r0.w, w3, a0);
            a1 = fmaf(r1.x, w0, a1); a1 = fmaf(r1.y, w1, a1);
            a1 = fmaf(r1.z, w2, a1); a1 = fmaf(r1.w, w3, a1);
            a2 = fmaf(r2.x, w0, a2); a2 = fmaf(r2.y, w1, a2);
            a2 = fmaf(r2.z, w2, a2); a2 = fmaf(r2.w, w3, a2);
            a3 = fmaf(r3.x, w0, a3); a3 = fmaf(r3.y, w1, a3);
            a3 = fmaf(r3.z, w2, a3); a3 = fmaf(r3.w, w3, a3);
        }

        const float d0 = g_dis[nb + 0], d1 = g_dis[nb + 1];
        const float d2 = g_dis[nb + 2], d3 = g_dis[nb + 3];
        g_h1[(nb + 0) * F_HID + col] = a0;
        g_h1[(nb + 1) * F_HID + col] = a1;
        g_h1[(nb + 2) * F_HID + col] = a2;
        g_h1[(nb + 3) * F_HID + col] = a3;
        g_acc1[(nb + 0) * F_HID + col] = fmaf(a0, d0 * d0, bias);
        g_acc1[(nb + 1) * F_HID + col] = fmaf(a1, d1 * d1, bias);
        g_acc1[(nb + 2) * F_HID + col] = fmaf(a2, d2 * d2, bias);
        g_acc1[(nb + 3) * F_HID + col] = fmaf(a3, d3 * d3, bias);
    }
}

// ---------------------------------------------------------------------------
// Layer 1 scatter: acc1[dst] += h1[src] * norm[e]
// 16 threads/edge: 1 LDG.128 gather + 1 red.global.add.v4.f32
// ---------------------------------------------------------------------------
__global__ void __launch_bounds__(256) k_scatter1(const int* __restrict__ src,
                                                  const int* __restrict__ dst) {
    long long t = (long long)blockIdx.x * blockDim.x + threadIdx.x;
    if (t >= (long long)EE * 16) return;
    const int e    = (int)(t >> 4);
    const int part = (int)(t & 15);
    const int s = src[e];
    const int d = dst[e];
    const float nrm = g_norm[e];
    const float4 v = *reinterpret_cast<const float4*>(&g_h1[s * F_HID + part * 4]);
    float* o = &g_acc1[d * F_HID + part * 4];
    asm volatile("red.global.add.v4.f32 [%0], {%1, %2, %3, %4};"
                 :: "l"(o), "f"(v.x * nrm), "f"(v.y * nrm),
                    "f"(v.z * nrm), "f"(v.w * nrm)
                 : "memory");
}

// ---------------------------------------------------------------------------
// Layer 2 GEMM: h2 = relu(acc1) @ W2 ; out = h2 * dis^2 + b2
// 256 threads: col = tid & 31, group g = tid >> 5. Tile = 8 nodes; thread
// handles node (nb+g). W2[:,col] register-resident.
// ---------------------------------------------------------------------------
__global__ void __launch_bounds__(256) k_gemm2(const float* __restrict__ W,
                                               const float* __restrict__ b,
                                               float* __restrict__ out) {
    __shared__ float Ws[F_HID * F_OUT];  // 8 KB
    __shared__ __align__(16) float xs[8 * F_HID];  // 2 KB

    for (int i = threadIdx.x; i < F_HID * F_OUT; i += 256) Ws[i] = W[i];
    __syncthreads();

    const int col = threadIdx.x & 31;
    const int g   = threadIdx.x >> 5;
    float w[F_HID];
#pragma unroll
    for (int k = 0; k < F_HID; k++) w[k] = Ws[k * F_OUT + col];
    const float bias = b[col];

    const int ntiles = NN / 8;   // 12500
    for (int tile = blockIdx.x; tile < ntiles; tile += gridDim.x) {
        const int nb = tile * 8;
        __syncthreads();
        xs[threadIdx.x]       = fmaxf(g_acc1[nb * F_HID + threadIdx.x], 0.0f);
        xs[threadIdx.x + 256] = fmaxf(g_acc1[nb * F_HID + 256 + threadIdx.x], 0.0f);
        __syncthreads();

        const int n = nb + g;
        float acc = 0.f;
        const float4* xv = reinterpret_cast<const float4*>(xs + g * F_HID);
#pragma unroll
        for (int k4 = 0; k4 < 16; k4++) {
            const float4 r = xv[k4];
            acc = fmaf(r.x, w[4 * k4 + 0], acc);
            acc = fmaf(r.y, w[4 * k4 + 1], acc);
            acc = fmaf(r.z, w[4 * k4 + 2], acc);
            acc = fmaf(r.w, w[4 * k4 + 3], acc);
        }
        const float d = g_dis[n];
        g_h2[n * F_OUT + col] = acc;
        out[n * F_OUT + col]  = fmaf(acc, d * d, bias);
    }
}

// ---------------------------------------------------------------------------
// Layer 2 scatter: out[dst] += h2[src] * norm[e]   (8 threads/edge)
// ---------------------------------------------------------------------------
__global__ void __launch_bounds__(256) k_scatter2(const int* __restrict__ src,
                                                  const int* __restrict__ dst,
                                                  float* __restrict__ out) {
    long long t = (long long)blockIdx.x * blockDim.x + threadIdx.x;
    if (t >= (long long)EE * 8) return;
    const int e    = (int)(t >> 3);
    const int part = (int)(t & 7);
    const int s = src[e];
    const int d = dst[e];
    const float nrm = g_norm[e];
    const float4 v = *reinterpret_cast<const float4*>(&g_h2[s * F_OUT + part * 4]);
    float* o = &out[d * F_OUT + part * 4];
    asm volatile("red.global.add.v4.f32 [%0], {%1, %2, %3, %4};"
                 :: "l"(o), "f"(v.x * nrm), "f"(v.y * nrm),
                    "f"(v.z * nrm), "f"(v.w * nrm)
                 : "memory");
}

// ---------------------------------------------------------------------------
extern "C" void kernel_launch(void* const* d_in, const int* in_sizes, int n_in,
                              void* d_out, int out_size) {
    const float* x  = (const float*)d_in[0];
    const int*   ei = (const int*)d_in[1];   // [2, E] int32 on device
    const float* W1 = (const float*)d_in[2];
    const float* b1 = (const float*)d_in[3];
    const float* W2 = (const float*)d_in[4];
    const float* b2 = (const float*)d_in[5];
    float*       out = (float*)d_out;
    (void)b1;

    const int* src = ei;
    const int* dst = ei + EE;

    // degree + normalization
    k_zero_deg<<<(NN + 255) / 256, 256>>>();
    k_degree<<<(EE + 255) / 256, 256>>>(dst);
    k_dis<<<(NN + 255) / 256, 256>>>();
    k_norm<<<(EE + 255) / 256, 256>>>(src, dst);

    // layer 1
    k_gemm1<<<592, 256>>>(x, W1, d_in[3] ? (const float*)d_in[3] : nullptr);
    {
        long long threads = (long long)EE * 16;
        k_scatter1<<<(unsigned)((threads + 255) / 256), 256>>>(src, dst);
    }

    // layer 2
    k_gemm2<<<592, 256>>>(W2, b2, out);
    {
        long long threads = (long long)EE * 8;
        k_scatter2<<<(unsigned)((threads + 255) / 256), 256>>>(src, dst, out);
    }
}

// round 4
// speedup vs baseline: 1.5559x; 1.1416x over previous
#include <cuda_runtime.h>
#include <cstdint>

#define NN 100000
#define EE 1600000
#define F_IN 64
#define F_HID 64
#define F_OUT 32

// Scratch (static device globals — no allocation allowed)
__device__ int   g_degi[NN];
__device__ __align__(16) float g_dis[NN];
__device__ int   g_off[NN];       // CSR row offset per dst node
__device__ int   g_cursor[NN];    // fill cursor per dst node
__device__ int   g_total;         // offset allocator
__device__ int   g_csr_src[EE];   // src node per CSR slot
__device__ __align__(16) float g_csr_nrm[EE];   // dis[src]*dis[dst] per CSR slot
__device__ __align__(16) float g_h1[NN * F_HID];
__device__ __align__(16) float g_acc1[NN * F_HID];
__device__ __align__(16) float g_h2[NN * F_OUT];

// ---------------------------------------------------------------------------
// CSR build
// ---------------------------------------------------------------------------
__global__ void k_zero() {
    int i = blockIdx.x * blockDim.x + threadIdx.x;
    if (i < NN) g_degi[i] = 0;
    if (i == 0) g_total = 0;
}

__global__ void k_degree(const int* __restrict__ dst) {
    int i = blockIdx.x * blockDim.x + threadIdx.x;
    if (i < EE) atomicAdd(&g_degi[dst[i]], 1);
}

// dis = rsqrt(deg+1); allocate CSR row offsets (order-free atomic allocation)
__global__ void k_dis_alloc() {
    int i = blockIdx.x * blockDim.x + threadIdx.x;
    if (i < NN) {
        const int d = g_degi[i];
        g_dis[i] = rsqrtf((float)d + 1.0f);
        const int off = atomicAdd(&g_total, d);
        g_off[i] = off;
        g_cursor[i] = off;
    }
}

__global__ void k_fill(const int* __restrict__ src, const int* __restrict__ dst) {
    int e = blockIdx.x * blockDim.x + threadIdx.x;
    if (e < EE) {
        const int s = src[e];
        const int d = dst[e];
        const int p = atomicAdd(&g_cursor[d], 1);
        g_csr_src[p] = s;
        g_csr_nrm[p] = g_dis[s] * g_dis[d];
    }
}

// ---------------------------------------------------------------------------
// Layer 1 GEMM: h1 = x @ W1 ; acc1 = h1 * dis^2 + b1 (self-loop seed)
// col = tid & 63; W1[:,col] register-resident; 4-node tiles via smem broadcast.
// ---------------------------------------------------------------------------
__global__ void __launch_bounds__(256) k_gemm1(const float* __restrict__ x,
                                               const float* __restrict__ W,
                                               const float* __restrict__ b) {
    __shared__ float Ws[F_IN * F_HID];
    __shared__ __align__(16) float xs[4 * F_IN];

    for (int i = threadIdx.x; i < F_IN * F_HID; i += 256) Ws[i] = W[i];
    __syncthreads();

    const int col = threadIdx.x & 63;
    float w[F_IN];
#pragma unroll
    for (int k = 0; k < F_IN; k++) w[k] = Ws[k * F_HID + col];
    const float bias = b[col];

    const int ntiles = NN / 4;
    for (int tile = blockIdx.x; tile < ntiles; tile += gridDim.x) {
        const int nb = tile * 4;
        __syncthreads();
        xs[threadIdx.x] = x[nb * F_IN + threadIdx.x];
        __syncthreads();

        float a0 = 0.f, a1 = 0.f, a2 = 0.f, a3 = 0.f;
        const float4* xv = reinterpret_cast<const float4*>(xs);
#pragma unroll
        for (int k4 = 0; k4 < 16; k4++) {
            const float4 r0 = xv[k4];
            const float4 r1 = xv[16 + k4];
            const float4 r2 = xv[32 + k4];
            const float4 r3 = xv[48 + k4];
            const float w0 = w[4 * k4 + 0], w1 = w[4 * k4 + 1];
            const float w2 = w[4 * k4 + 2], w3 = w[4 * k4 + 3];
            a0 = fmaf(r0.x, w0, a0); a0 = fmaf(r0.y, w1, a0);
            a0 = fmaf(r0.z, w2, a0); a0 = fmaf(r0.w, w3, a0);
            a1 = fmaf(r1.x, w0, a1); a1 = fmaf(r1.y, w1, a1);
            a1 = fmaf(r1.z, w2, a1); a1 = fmaf(r1.w, w3, a1);
            a2 = fmaf(r2.x, w0, a2); a2 = fmaf(r2.y, w1, a2);
            a2 = fmaf(r2.z, w2, a2); a2 = fmaf(r2.w, w3, a2);
            a3 = fmaf(r3.x, w0, a3); a3 = fmaf(r3.y, w1, a3);
            a3 = fmaf(r3.z, w2, a3); a3 = fmaf(r3.w, w3, a3);
        }

        const float d0 = g_dis[nb + 0], d1 = g_dis[nb + 1];
        const float d2 = g_dis[nb + 2], d3 = g_dis[nb + 3];
        g_h1[(nb + 0) * F_HID + col] = a0;
        g_h1[(nb + 1) * F_HID + col] = a1;
        g_h1[(nb + 2) * F_HID + col] = a2;
        g_h1[(nb + 3) * F_HID + col] = a3;
        g_acc1[(nb + 0) * F_HID + col] = fmaf(a0, d0 * d0, bias);
        g_acc1[(nb + 1) * F_HID + col] = fmaf(a1, d1 * d1, bias);
        g_acc1[(nb + 2) * F_HID + col] = fmaf(a2, d2 * d2, bias);
        g_acc1[(nb + 3) * F_HID + col] = fmaf(a3, d3 * d3, bias);
    }
}

// ---------------------------------------------------------------------------
// Layer 1 aggregation: one warp per dst node, gather-reduce (no atomics).
// acc1[n] += sum over in-edges of h1[src] * nrm. Lane holds 2 columns.
// ---------------------------------------------------------------------------
__global__ void __launch_bounds__(256) k_agg1() {
    const int warp = (blockIdx.x * 256 + threadIdx.x) >> 5;
    const int lane = threadIdx.x & 31;
    if (warp >= NN) return;
    const int n    = warp;
    const int off  = g_off[n];
    const int deg  = g_degi[n];

    float2 acc = *reinterpret_cast<const float2*>(&g_acc1[n * F_HID + lane * 2]);

    int j = off;
    const int end = off + deg;
    // unroll-2 for MLP
    for (; j + 1 < end; j += 2) {
        const int   s0 = g_csr_src[j];
        const int   s1 = g_csr_src[j + 1];
        const float m0 = g_csr_nrm[j];
        const float m1 = g_csr_nrm[j + 1];
        const float2 v0 = *reinterpret_cast<const float2*>(&g_h1[s0 * F_HID + lane * 2]);
        const float2 v1 = *reinterpret_cast<const float2*>(&g_h1[s1 * F_HID + lane * 2]);
        acc.x = fmaf(v0.x, m0, acc.x); acc.y = fmaf(v0.y, m0, acc.y);
        acc.x = fmaf(v1.x, m1, acc.x); acc.y = fmaf(v1.y, m1, acc.y);
    }
    if (j < end) {
        const int   s = g_csr_src[j];
        const float m = g_csr_nrm[j];
        const float2 v = *reinterpret_cast<const float2*>(&g_h1[s * F_HID + lane * 2]);
        acc.x = fmaf(v.x, m, acc.x); acc.y = fmaf(v.y, m, acc.y);
    }
    *reinterpret_cast<float2*>(&g_acc1[n * F_HID + lane * 2]) = acc;
}

// ---------------------------------------------------------------------------
// Layer 2 GEMM: h2 = relu(acc1) @ W2 ; out = h2 * dis^2 + b2 (self-loop seed)
// ---------------------------------------------------------------------------
__global__ void __launch_bounds__(256) k_gemm2(const float* __restrict__ W,
                                               const float* __restrict__ b,
                                               float* __restrict__ out) {
    __shared__ float Ws[F_HID * F_OUT];
    __shared__ __align__(16) float xs[8 * F_HID];

    for (int i = threadIdx.x; i < F_HID * F_OUT; i += 256) Ws[i] = W[i];
    __syncthreads();

    const int col = threadIdx.x & 31;
    const int g   = threadIdx.x >> 5;
    float w[F_HID];
#pragma unroll
    for (int k = 0; k < F_HID; k++) w[k] = Ws[k * F_OUT + col];
    const float bias = b[col];

    const int ntiles = NN / 8;
    for (int tile = blockIdx.x; tile < ntiles; tile += gridDim.x) {
        const int nb = tile * 8;
        __syncthreads();
        xs[threadIdx.x]       = fmaxf(g_acc1[nb * F_HID + threadIdx.x], 0.0f);
        xs[threadIdx.x + 256] = fmaxf(g_acc1[nb * F_HID + 256 + threadIdx.x], 0.0f);
        __syncthreads();

        const int n = nb + g;
        float acc = 0.f;
        const float4* xv = reinterpret_cast<const float4*>(xs + g * F_HID);
#pragma unroll
        for (int k4 = 0; k4 < 16; k4++) {
            const float4 r = xv[k4];
            acc = fmaf(r.x, w[4 * k4 + 0], acc);
            acc = fmaf(r.y, w[4 * k4 + 1], acc);
            acc = fmaf(r.z, w[4 * k4 + 2], acc);
            acc = fmaf(r.w, w[4 * k4 + 3], acc);
        }
        const float d = g_dis[n];
        g_h2[n * F_OUT + col] = acc;
        out[n * F_OUT + col]  = fmaf(acc, d * d, bias);
    }
}

// ---------------------------------------------------------------------------
// Layer 2 aggregation: one warp per dst node; lane holds 1 column.
// ---------------------------------------------------------------------------
__global__ void __launch_bounds__(256) k_agg2(float* __restrict__ out) {
    const int warp = (blockIdx.x * 256 + threadIdx.x) >> 5;
    const int lane = threadIdx.x & 31;
    if (warp >= NN) return;
    const int n    = warp;
    const int off  = g_off[n];
    const int deg  = g_degi[n];

    float acc = out[n * F_OUT + lane];

    int j = off;
    const int end = off + deg;
    for (; j + 1 < end; j += 2) {
        const int   s0 = g_csr_src[j];
        const int   s1 = g_csr_src[j + 1];
        const float m0 = g_csr_nrm[j];
        const float m1 = g_csr_nrm[j + 1];
        const float v0 = g_h2[s0 * F_OUT + lane];
        const float v1 = g_h2[s1 * F_OUT + lane];
        acc = fmaf(v0, m0, acc);
        acc = fmaf(v1, m1, acc);
    }
    if (j < end) {
        acc = fmaf(g_h2[g_csr_src[j] * F_OUT + lane], g_csr_nrm[j], acc);
    }
    out[n * F_OUT + lane] = acc;
}

// ---------------------------------------------------------------------------
extern "C" void kernel_launch(void* const* d_in, const int* in_sizes, int n_in,
                              void* d_out, int out_size) {
    const float* x  = (const float*)d_in[0];
    const int*   ei = (const int*)d_in[1];   // [2, E] int32 on device
    const float* W1 = (const float*)d_in[2];
    const float* b1 = (const float*)d_in[3];
    const float* W2 = (const float*)d_in[4];
    const float* b2 = (const float*)d_in[5];
    float*       out = (float*)d_out;

    const int* src = ei;
    const int* dst = ei + EE;

    // CSR build (shared by both layers)
    k_zero<<<(NN + 255) / 256, 256>>>();
    k_degree<<<(EE + 255) / 256, 256>>>(dst);
    k_dis_alloc<<<(NN + 255) / 256, 256>>>();
    k_fill<<<(EE + 255) / 256, 256>>>(src, dst);

    // layer 1
    k_gemm1<<<592, 256>>>(x, W1, b1);
    k_agg1<<<(NN * 32 + 255) / 256, 256>>>();

    // layer 2
    k_gemm2<<<592, 256>>>(W2, b2, out);
    k_agg2<<<(NN * 32 + 255) / 256, 256>>>(out);
}

// round 6
// speedup vs baseline: 1.8320x; 1.1774x over previous
#include <cuda_runtime.h>
#include <cuda_fp16.h>
#include <cstdint>

#define NN 100000
#define EE 1600000
#define F_IN 64
#define F_HID 64
#define F_OUT 32

// Scratch (static device globals — no allocation allowed)
__device__ int   g_degi[NN];
__device__ __align__(16) float g_dis[NN];
__device__ int   g_off[NN];       // CSR row offset per dst node
__device__ int   g_cursor[NN];    // fill cursor per dst node
__device__ int   g_total;         // offset allocator
__device__ int   g_csr_src[EE];   // src node per CSR slot
__device__ __align__(16) __half g_h1s[NN * F_HID];  // (x@W1)*dis  (fp16)
__device__ __align__(16) float  g_acc1[NN * F_HID]; // relu(layer-1 out)
__device__ __align__(16) __half g_h2s[NN * F_OUT];  // (acc1@W2)*dis (fp16)

// ---------------------------------------------------------------------------
// CSR build
// ---------------------------------------------------------------------------
__global__ void k_zero() {
    int i = blockIdx.x * blockDim.x + threadIdx.x;
    if (i < NN) g_degi[i] = 0;
    if (i == 0) g_total = 0;
}

__global__ void k_degree(const int* __restrict__ dst) {
    int i = blockIdx.x * blockDim.x + threadIdx.x;
    if (i < EE) atomicAdd(&g_degi[dst[i]], 1);
}

__global__ void k_dis_alloc() {
    int i = blockIdx.x * blockDim.x + threadIdx.x;
    if (i < NN) {
        const int d = g_degi[i];
        g_dis[i] = rsqrtf((float)d + 1.0f);
        const int off = atomicAdd(&g_total, d);
        g_off[i] = off;
        g_cursor[i] = off;
    }
}

__global__ void k_fill(const int* __restrict__ src, const int* __restrict__ dst) {
    int e = blockIdx.x * blockDim.x + threadIdx.x;
    if (e < EE) {
        const int p = atomicAdd(&g_cursor[dst[e]], 1);
        g_csr_src[p] = src[e];
    }
}

// ---------------------------------------------------------------------------
// Layer 1 GEMM: h1s = (x @ W1) * dis[n], stored fp16.
// col = tid & 63; W1[:,col] register-resident; 4-node tiles via smem broadcast.
// ---------------------------------------------------------------------------
__global__ void __launch_bounds__(256) k_gemm1(const float* __restrict__ x,
                                               const float* __restrict__ W) {
    __shared__ float Ws[F_IN * F_HID];
    __shared__ __align__(16) float xs[4 * F_IN];

    for (int i = threadIdx.x; i < F_IN * F_HID; i += 256) Ws[i] = W[i];
    __syncthreads();

    const int col = threadIdx.x & 63;
    float w[F_IN];
#pragma unroll
    for (int k = 0; k < F_IN; k++) w[k] = Ws[k * F_HID + col];

    const int ntiles = NN / 4;
    for (int tile = blockIdx.x; tile < ntiles; tile += gridDim.x) {
        const int nb = tile * 4;
        __syncthreads();
        xs[threadIdx.x] = x[nb * F_IN + threadIdx.x];
        __syncthreads();

        float a0 = 0.f, a1 = 0.f, a2 = 0.f, a3 = 0.f;
        const float4* xv = reinterpret_cast<const float4*>(xs);
#pragma unroll
        for (int k4 = 0; k4 < 16; k4++) {
            const float4 r0 = xv[k4];
            const float4 r1 = xv[16 + k4];
            const float4 r2 = xv[32 + k4];
            const float4 r3 = xv[48 + k4];
            const float w0 = w[4 * k4 + 0], w1 = w[4 * k4 + 1];
            const float w2 = w[4 * k4 + 2], w3 = w[4 * k4 + 3];
            a0 = fmaf(r0.x, w0, a0); a0 = fmaf(r0.y, w1, a0);
            a0 = fmaf(r0.z, w2, a0); a0 = fmaf(r0.w, w3, a0);
            a1 = fmaf(r1.x, w0, a1); a1 = fmaf(r1.y, w1, a1);
            a1 = fmaf(r1.z, w2, a1); a1 = fmaf(r1.w, w3, a1);
            a2 = fmaf(r2.x, w0, a2); a2 = fmaf(r2.y, w1, a2);
            a2 = fmaf(r2.z, w2, a2); a2 = fmaf(r2.w, w3, a2);
            a3 = fmaf(r3.x, w0, a3); a3 = fmaf(r3.y, w1, a3);
            a3 = fmaf(r3.z, w2, a3); a3 = fmaf(r3.w, w3, a3);
        }

        g_h1s[(nb + 0) * F_HID + col] = __float2half_rn(a0 * g_dis[nb + 0]);
        g_h1s[(nb + 1) * F_HID + col] = __float2half_rn(a1 * g_dis[nb + 1]);
        g_h1s[(nb + 2) * F_HID + col] = __float2half_rn(a2 * g_dis[nb + 2]);
        g_h1s[(nb + 3) * F_HID + col] = __float2half_rn(a3 * g_dis[nb + 3]);
    }
}

// ---------------------------------------------------------------------------
// Layer 1 aggregation: one warp per dst node. Lane holds 2 columns (half2).
// acc = h1s[n] + sum_edges h1s[src];  acc1[n] = relu(dis[n]*acc + b1)
// ---------------------------------------------------------------------------
__global__ void __launch_bounds__(256) k_agg1(const float* __restrict__ b1) {
    const int warp = (blockIdx.x * 256 + threadIdx.x) >> 5;
    const int lane = threadIdx.x & 31;
    if (warp >= NN) return;
    const int n   = warp;
    const int off = g_off[n];
    const int end = off + g_degi[n];

    const __half2* h2p = reinterpret_cast<const __half2*>(g_h1s);

    // self term
    float2 acc = __half22float2(h2p[n * 32 + lane]);

    int j = off;
    for (; j + 3 < end; j += 4) {
        const int s0 = g_csr_src[j + 0];
        const int s1 = g_csr_src[j + 1];
        const int s2 = g_csr_src[j + 2];
        const int s3 = g_csr_src[j + 3];
        const float2 v0 = __half22float2(h2p[s0 * 32 + lane]);
        const float2 v1 = __half22float2(h2p[s1 * 32 + lane]);
        const float2 v2 = __half22float2(h2p[s2 * 32 + lane]);
        const float2 v3 = __half22float2(h2p[s3 * 32 + lane]);
        acc.x += (v0.x + v1.x) + (v2.x + v3.x);
        acc.y += (v0.y + v1.y) + (v2.y + v3.y);
    }
    for (; j < end; j++) {
        const float2 v = __half22float2(h2p[g_csr_src[j] * 32 + lane]);
        acc.x += v.x; acc.y += v.y;
    }

    const float dd = g_dis[n];
    const float2 bb = *reinterpret_cast<const float2*>(&b1[lane * 2]);
    float2 o;
    o.x = fmaxf(fmaf(acc.x, dd, bb.x), 0.0f);
    o.y = fmaxf(fmaf(acc.y, dd, bb.y), 0.0f);
    *reinterpret_cast<float2*>(&g_acc1[n * F_HID + lane * 2]) = o;
}

// ---------------------------------------------------------------------------
// Layer 2 GEMM: h2s = (acc1 @ W2) * dis[n], stored fp16. acc1 already relu'd.
// ---------------------------------------------------------------------------
__global__ void __launch_bounds__(256) k_gemm2(const float* __restrict__ W) {
    __shared__ float Ws[F_HID * F_OUT];
    __shared__ __align__(16) float xs[8 * F_HID];

    for (int i = threadIdx.x; i < F_HID * F_OUT; i += 256) Ws[i] = W[i];
    __syncthreads();

    const int col = threadIdx.x & 31;
    const int g   = threadIdx.x >> 5;
    float w[F_HID];
#pragma unroll
    for (int k = 0; k < F_HID; k++) w[k] = Ws[k * F_OUT + col];

    const int ntiles = NN / 8;
    for (int tile = blockIdx.x; tile < ntiles; tile += gridDim.x) {
        const int nb = tile * 8;
        __syncthreads();
        xs[threadIdx.x]       = g_acc1[nb * F_HID + threadIdx.x];
        xs[threadIdx.x + 256] = g_acc1[nb * F_HID + 256 + threadIdx.x];
        __syncthreads();

        const int n = nb + g;
        float acc = 0.f;
        const float4* xv = reinterpret_cast<const float4*>(xs + g * F_HID);
#pragma unroll
        for (int k4 = 0; k4 < 16; k4++) {
            const float4 r = xv[k4];
            acc = fmaf(r.x, w[4 * k4 + 0], acc);
            acc = fmaf(r.y, w[4 * k4 + 1], acc);
            acc = fmaf(r.z, w[4 * k4 + 2], acc);
            acc = fmaf(r.w, w[4 * k4 + 3], acc);
        }
        g_h2s[n * F_OUT + col] = __float2half_rn(acc * g_dis[n]);
    }
}

// ---------------------------------------------------------------------------
// Layer 2 aggregation: one warp per dst node; lane holds 1 column.
// out[n] = dis[n]*(h2s[n] + sum h2s[src]) + b2
// ---------------------------------------------------------------------------
__global__ void __launch_bounds__(256) k_agg2(const float* __restrict__ b2,
                                              float* __restrict__ out) {
    const int warp = (blockIdx.x * 256 + threadIdx.x) >> 5;
    const int lane = threadIdx.x & 31;
    if (warp >= NN) return;
    const int n   = warp;
    const int off = g_off[n];
    const int end = off + g_degi[n];

    float acc = __half2float(g_h2s[n * F_OUT + lane]);

    int j = off;
    for (; j + 3 < end; j += 4) {
        const int s0 = g_csr_src[j + 0];
        const int s1 = g_csr_src[j + 1];
        const int s2 = g_csr_src[j + 2];
        const int s3 = g_csr_src[j + 3];
        const float v0 = __half2float(g_h2s[s0 * F_OUT + lane]);
        const float v1 = __half2float(g_h2s[s1 * F_OUT + lane]);
        const float v2 = __half2float(g_h2s[s2 * F_OUT + lane]);
        const float v3 = __half2float(g_h2s[s3 * F_OUT + lane]);
        acc += (v0 + v1) + (v2 + v3);
    }
    for (; j < end; j++)
        acc += __half2float(g_h2s[g_csr_src[j] * F_OUT + lane]);

    out[n * F_OUT + lane] = fmaf(acc, g_dis[n], b2[lane]);
}

// ---------------------------------------------------------------------------
extern "C" void kernel_launch(void* const* d_in, const int* in_sizes, int n_in,
                              void* d_out, int out_size) {
    const float* x  = (const float*)d_in[0];
    const int*   ei = (const int*)d_in[1];   // [2, E] int32 on device
    const float* W1 = (const float*)d_in[2];
    const float* b1 = (const float*)d_in[3];
    const float* W2 = (const float*)d_in[4];
    const float* b2 = (const float*)d_in[5];
    float*       out = (float*)d_out;

    const int* src = ei;
    const int* dst = ei + EE;

    // CSR build (indices only; no per-edge weights needed)
    k_zero<<<(NN + 255) / 256, 256>>>();
    k_degree<<<(EE + 255) / 256, 256>>>(dst);
    k_dis_alloc<<<(NN + 255) / 256, 256>>>();
    k_fill<<<(EE + 255) / 256, 256>>>(src, dst);

    // layer 1
    k_gemm1<<<592, 256>>>(x, W1);
    k_agg1<<<(NN * 32 + 255) / 256, 256>>>(b1);

    // layer 2
    k_gemm2<<<592, 256>>>(W2);
    k_agg2<<<(NN * 32 + 255) / 256, 256>>>(b2, out);
}